// round 3
// baseline (speedup 1.0000x reference)
#include <cuda_runtime.h>
#include <math.h>

// Problem constants
#define NROWS   65536
#define DIMK    64
#define CB      1024
#define TOPKK   3
#define THREADS 128
#define NBLOCKS 512          // 65536 / 128 rows per block
#define CHUNK   128          // codes per smem chunk
#define NCHUNK  8            // 1024 / 128
#define EPADF   68           // floats per ebuf row: 272B, 16B-aligned stride, conflict-light

// Output layout (concatenated reference tuple, fp32):
//   z_q_st [4194304] | loss [1] | perplexity [1] | encodings [201326592] | idx [196608]
#define OFF_LOSS 4194304ull
#define OFF_PERP 4194305ull
#define OFF_ENC  4194306ull   // byte offset % 16 == 8 -> only 8B-aligned! use float2 there
#define OFF_IDX  205520898ull

static __device__ float        g_loss_sum;
static __device__ unsigned int g_hist[CB];

__device__ __forceinline__ unsigned long long pack2(float lo, float hi) {
    unsigned long long u;
    asm("mov.b64 %0, {%1, %2};" : "=l"(u) : "f"(lo), "f"(hi));
    return u;
}
__device__ __forceinline__ void unpack2(unsigned long long u, float& lo, float& hi) {
    asm("mov.b64 {%0, %1}, %2;" : "=f"(lo), "=f"(hi) : "l"(u));
}
__device__ __forceinline__ unsigned long long ffma2(unsigned long long a, unsigned long long b,
                                                    unsigned long long c) {
    unsigned long long d;
    asm("fma.rn.f32x2 %0, %1, %2, %3;" : "=l"(d) : "l"(a), "l"(b), "l"(c));
    return d;
}
__device__ __forceinline__ unsigned long long fadd2(unsigned long long a, unsigned long long b) {
    unsigned long long d;
    asm("add.rn.f32x2 %0, %1, %2;" : "=l"(d) : "l"(a), "l"(b));
    return d;
}

__global__ void vq_init() {
    g_hist[threadIdx.x] = 0u;
    if (threadIdx.x == 0) g_loss_sum = 0.f;
}

__global__ void __launch_bounds__(THREADS) vq_main(
    const float* __restrict__ z, const float* __restrict__ emb, float* __restrict__ out)
{
    __shared__ alignas(16) float ebuf[CHUNK * EPADF];
    __shared__ float esq_s[CHUNK];

    const int t   = threadIdx.x;
    const int row = blockIdx.x * THREADS + t;

    // ---- load this thread's z-row, packed as f32x2 pairs; compute |z|^2 ----
    unsigned long long zp[32];
    float zsq = 0.f;
    {
        const float4* zr = (const float4*)(z + (size_t)row * DIMK);
        #pragma unroll
        for (int i = 0; i < 16; i++) {
            float4 v = __ldg(zr + i);
            zp[2*i]   = pack2(v.x, v.y);
            zp[2*i+1] = pack2(v.z, v.w);
            zsq += v.x*v.x; zsq += v.y*v.y; zsq += v.z*v.z; zsq += v.w*v.w;
        }
    }

    float s0 = 3.4e38f, s1 = 3.4e38f, s2 = 3.4e38f;
    int   i0 = 0, i1 = 0, i2 = 0;

    // Encodings region is only 8B-aligned (OFF_ENC % 4 floats == 2) -> float2 stores.
    float2* encb2 = (float2*)(out + OFF_ENC + (size_t)blockIdx.x * THREADS * (TOPKK * CB));

    for (int c = 0; c < NCHUNK; c++) {
        __syncthreads();
        // ---- stage codebook chunk into smem; fold |e|^2 computation into the load ----
        {
            const float4* er  = (const float4*)(emb + (size_t)(c * CHUNK + t) * DIMK);
            float4*       dst = (float4*)&ebuf[t * EPADF];
            float es = 0.f;
            #pragma unroll
            for (int i = 0; i < 16; i++) {
                float4 v = __ldg(er + i);
                es += v.x*v.x; es += v.y*v.y; es += v.z*v.z; es += v.w*v.w;
                dst[i] = v;
            }
            esq_s[t] = es;
        }
        __syncthreads();

        // ---- interleaved coalesced zeroing of this block's one-hot region (1/8 per chunk)
        //      so the 805MB of DRAM writes drain while the fma pipe crunches ----
        {
            const float2 zz = make_float2(0.f, 0.f);
            // block slice per chunk: 128 rows * 3072 floats / 8 chunks = 49152 floats = 24576 float2
            float2* d2 = encb2 + (size_t)c * 24576;
            #pragma unroll 8
            for (int i = 0; i < 192; i++) d2[i * THREADS + t] = zz;
        }

        // ---- distances for 128 codes: d = (|z|^2 + |e|^2) - 2*dot, running top-3 ----
        for (int j = 0; j < CHUNK; j++) {
            const ulonglong2* ep = (const ulonglong2*)&ebuf[j * EPADF];
            unsigned long long a0 = 0ull, a1 = 0ull, a2 = 0ull, a3 = 0ull;
            #pragma unroll
            for (int m = 0; m < 16; m += 4) {
                ulonglong2 e0 = ep[m], e1 = ep[m+1], e2 = ep[m+2], e3 = ep[m+3];
                a0 = ffma2(zp[2*m+0], e0.x, a0);
                a1 = ffma2(zp[2*m+1], e0.y, a1);
                a2 = ffma2(zp[2*m+2], e1.x, a2);
                a3 = ffma2(zp[2*m+3], e1.y, a3);
                a0 = ffma2(zp[2*m+4], e2.x, a0);
                a1 = ffma2(zp[2*m+5], e2.y, a1);
                a2 = ffma2(zp[2*m+6], e3.x, a2);
                a3 = ffma2(zp[2*m+7], e3.y, a3);
            }
            a0 = fadd2(a0, a1); a2 = fadd2(a2, a3); a0 = fadd2(a0, a2);
            float lo, hi; unpack2(a0, lo, hi);
            float dot = __fadd_rn(lo, hi);
            float d   = __fsub_rn(__fadd_rn(zsq, esq_s[j]), __fmul_rn(2.0f, dot));
            int gj = c * CHUNK + j;
            if (d < s2) {
                if (d < s1) {
                    s2 = s1; i2 = i1;
                    if (d < s0) { s1 = s0; i1 = i0; s0 = d; i0 = gj; }
                    else        { s1 = d;  i1 = gj; }
                } else { s2 = d; i2 = gj; }
            }
        }
    }

    __syncthreads();   // all zero-stores of this block ordered before the ones below

    // ---- epilogue: z_q (mean of top-3 emb rows), loss partial, idx, ones, histogram ----
    const float4* e0 = (const float4*)(emb + (size_t)i0 * DIMK);
    const float4* e1 = (const float4*)(emb + (size_t)i1 * DIMK);
    const float4* e2 = (const float4*)(emb + (size_t)i2 * DIMK);
    float4* zqout = (float4*)(out + (size_t)row * DIMK);
    float ls = 0.f;
    #pragma unroll
    for (int i = 0; i < 16; i++) {
        float4 v0 = __ldg(e0 + i), v1 = __ldg(e1 + i), v2 = __ldg(e2 + i);
        float4 q;
        q.x = __fdiv_rn(__fadd_rn(__fadd_rn(v0.x, v1.x), v2.x), 3.0f);
        q.y = __fdiv_rn(__fadd_rn(__fadd_rn(v0.y, v1.y), v2.y), 3.0f);
        q.z = __fdiv_rn(__fadd_rn(__fadd_rn(v0.z, v1.z), v2.z), 3.0f);
        q.w = __fdiv_rn(__fadd_rn(__fadd_rn(v0.w, v1.w), v2.w), 3.0f);
        float za, zb, zc, zd;
        unpack2(zp[2*i], za, zb); unpack2(zp[2*i+1], zc, zd);
        float dx = q.x - za; ls += dx*dx;
        dx = q.y - zb; ls += dx*dx;
        dx = q.z - zc; ls += dx*dx;
        dx = q.w - zd; ls += dx*dx;
        zqout[i] = q;   // z_q_st == z_q numerically (straight-through)
    }

    int idxs[3] = { i0, i1, i2 };
    #pragma unroll
    for (int s = 0; s < TOPKK; s++) {
        out[OFF_IDX + (size_t)row * TOPKK + s] = (float)idxs[s];
        out[OFF_ENC + (size_t)row * (TOPKK * CB) + (size_t)s * CB + idxs[s]] = 1.0f;
        atomicAdd(&g_hist[idxs[s]], 1u);
    }

    #pragma unroll
    for (int off = 16; off > 0; off >>= 1)
        ls += __shfl_xor_sync(0xffffffffu, ls, off);
    if ((t & 31) == 0) atomicAdd(&g_loss_sum, ls);
}

__global__ void vq_final(float* __restrict__ out) {
    __shared__ float red[32];
    int t = threadIdx.x;   // 1024 threads
    float p    = __fdiv_rn((float)g_hist[t], (float)(NROWS * TOPKK));
    float term = p * logf(p + 1e-10f);
    #pragma unroll
    for (int off = 16; off > 0; off >>= 1)
        term += __shfl_xor_sync(0xffffffffu, term, off);
    if ((t & 31) == 0) red[t >> 5] = term;
    __syncthreads();
    if (t < 32) {
        float v = red[t];
        #pragma unroll
        for (int off = 16; off > 0; off >>= 1)
            v += __shfl_xor_sync(0xffffffffu, v, off);
        if (t == 0) {
            float m = g_loss_sum * (1.0f / 4194304.0f);   // mean((z_q - z)^2), exact pow2
            out[OFF_LOSS] = __fadd_rn(__fmul_rn(0.25f, m), m);   // beta*m + m
            out[OFF_PERP] = expf(-v);
        }
    }
}

extern "C" void kernel_launch(void* const* d_in, const int* in_sizes, int n_in,
                              void* d_out, int out_size) {
    const float* z   = (const float*)d_in[0];
    const float* emb = (const float*)d_in[1];
    float* out = (float*)d_out;
    (void)in_sizes; (void)n_in; (void)out_size;
    vq_init<<<1, CB>>>();
    vq_main<<<NBLOCKS, THREADS>>>(z, emb, out);
    vq_final<<<1, CB>>>(out);
}